// round 15
// baseline (speedup 1.0000x reference)
#include <cuda_runtime.h>

typedef unsigned int u32;

#define SEQ 2048
#define HIDDEN 2048
#define NH 16
#define NKV 2
#define HD 128
#define KVW (NKV*HD)          // 256
#define ATT_SCALE 0.08838834764831845f

// ---------------- scratch (no allocations allowed) ----------------
__device__ float g_Q[SEQ*HIDDEN];
__device__ float g_K[SEQ*KVW];
__device__ float g_V[SEQ*KVW];
__device__ float g_C[SEQ*HIDDEN];

// ---------------- helpers ----------------
__device__ __forceinline__ void mma_f16(float* c, const u32* a, const u32* b) {
    asm volatile(
        "mma.sync.aligned.m16n8k16.row.col.f32.f16.f16.f32 "
        "{%0,%1,%2,%3}, {%4,%5,%6,%7}, {%8,%9}, {%0,%1,%2,%3};"
        : "+f"(c[0]), "+f"(c[1]), "+f"(c[2]), "+f"(c[3])
        : "r"(a[0]), "r"(a[1]), "r"(a[2]), "r"(a[3]),
          "r"(b[0]), "r"(b[1]));
}
// pack two fp32 -> f16x2, 'lo' in low half (convention verified R10-R14)
__device__ __forceinline__ u32 pack_h2(float lo, float hi) {
    u32 r;
    asm("cvt.rn.f16x2.f32 %0, %1, %2;" : "=r"(r) : "f"(hi), "f"(lo));
    return r;
}
__device__ __forceinline__ void prefetch_l1(const void* p) {
    asm volatile("prefetch.global.L1 [%0];" :: "l"(p));
}

// ---------------------------------------------------------------------------
// fp16 mma.sync GEMM, K-chunk 64 (4 ksteps of m16n8k16 per barrier).
// 128x128 block tile, 8 warps (2M x 4N -> 64x32 each), double-buffered smem,
// ONE barrier per 64-k chunk, reg staging (NO cp.async).
// sA: [128 rows][36 u32] (32 h2 data words + pad)  word w = half2(k=2w, 2w+1)
// sB: [32 k-pairs][136 u32]  sB[kp][n] = half2(W[2kp][n], W[2kp+1][n])
// mode 1: fused QKV (blocks 0-15 -> Q, 16-17 -> K, 18-19 -> V), mode 0: O-proj.
// ---------------------------------------------------------------------------
#define G_SA_LD 36
#define G_SB_LD 136
#define G_STAGE_A (128*G_SA_LD)              // 4608 words
#define G_STAGE (G_STAGE_A + 32*G_SB_LD)     // 8960 words
#define G_SMEM (2*G_STAGE*4)                 // 71680 B

__device__ __forceinline__ void gemm_stage_store(
    u32* buf, const float4* ar, const float2* br0, const float2* br1,
    int ar_row, int ar_seg, int bkp, int bcol)
{
    // A: 8 float4 per thread -> rows (idx>>4), seg (idx&15)
    #pragma unroll
    for (int p = 0; p < 8; p++) {
        const int idx = p * 256 + (ar_row * 16 + ar_seg);  // reconstructed below
        (void)idx;
    }
    // (implemented inline at call sites via explicit row/seg passed arrays)
    (void)buf; (void)ar; (void)br0; (void)br1; (void)ar_row; (void)ar_seg;
    (void)bkp; (void)bcol;
}

__global__ void __launch_bounds__(256) mma_gemm_kernel(
    const float* __restrict__ A_ext,
    const float* __restrict__ W0, const float* __restrict__ W1,
    const float* __restrict__ W2,
    const float* __restrict__ b0, const float* __restrict__ b1,
    const float* __restrict__ b2,
    float* __restrict__ outF, int mode)
{
    extern __shared__ u32 smg[];
    const int t = threadIdx.x;
    const int wid = t >> 5, lane = t & 31;
    const int warpM = wid & 1, warpN = wid >> 1;
    const int g = lane >> 2, tg = lane & 3;
    const int row0 = blockIdx.y * 128;

    const float* A; const float* W; const float* bias; float* C; int Nw; int col0;
    if (mode == 1) {
        A = A_ext;
        const int bn = blockIdx.x;
        if (bn < 16)      { W = W0; bias = b0; C = g_Q; Nw = HIDDEN; col0 = bn * 128; }
        else if (bn < 18) { W = W1; bias = b1; C = g_K; Nw = KVW;    col0 = (bn - 16) * 128; }
        else              { W = W2; bias = b2; C = g_V; Nw = KVW;    col0 = (bn - 18) * 128; }
    } else {
        A = g_C; W = W0; bias = nullptr; C = outF; Nw = HIDDEN; col0 = blockIdx.x * 128;
    }

    float c[4][4][4];
    #pragma unroll
    for (int i = 0; i < 4; i++)
        #pragma unroll
        for (int j = 0; j < 4; j++)
            #pragma unroll
            for (int r = 0; r < 4; r++) c[i][j][r] = 0.f;

    // staging coords (chunk = 64 k)
    // A: 8 passes; pass p handles idx = p*256 + t -> row = idx>>4, seg = idx&15
    const int a_row0 = t >> 4;          // rows advance +16 per pass
    const int a_seg  = t & 15;          // k-offset seg*4 (0..60)
    // B: 8 passes; kp = (t>>6) + p*4 (0..31), col = (t&63)*2
    const int bkp  = t >> 6;
    const int bcol = (t & 63) * 2;

    const float* Ap  = A + (size_t)(row0 + a_row0) * HIDDEN + a_seg * 4;
    const float* Bp0 = W + (size_t)(2 * bkp) * Nw + col0 + bcol;
    const float* Bp1 = Bp0 + Nw;
    const size_t aRow16 = (size_t)16 * HIDDEN;   // +16 rows per pass
    const size_t bRow8  = (size_t)8 * Nw;        // +4 k-pairs per pass
    const int NCH = HIDDEN >> 6;                 // 32 chunks of 64

    float4 ar[8]; float2 br0[8], br1[8];

    #define GEMM_LOAD(ko) do {                                             \
        _Pragma("unroll")                                                  \
        for (int p = 0; p < 8; p++) {                                      \
            ar[p]  = *(const float4*)(Ap + (ko) + p * aRow16);             \
            br0[p] = *(const float2*)(Bp0 + (size_t)(ko) * Nw + p * bRow8);\
            br1[p] = *(const float2*)(Bp1 + (size_t)(ko) * Nw + p * bRow8);\
        }                                                                  \
    } while (0)

    #define GEMM_STORE(buf) do {                                           \
        _Pragma("unroll")                                                  \
        for (int p = 0; p < 8; p++) {                                      \
            *(uint2*)((buf) + (a_row0 + p * 16) * G_SA_LD + a_seg * 2) =   \
                make_uint2(pack_h2(ar[p].x, ar[p].y),                      \
                           pack_h2(ar[p].z, ar[p].w));                     \
            *(uint2*)((buf) + G_STAGE_A + (bkp + p * 4) * G_SB_LD + bcol) =\
                make_uint2(pack_h2(br0[p].x, br1[p].x),                    \
                           pack_h2(br0[p].y, br1[p].y));                   \
        }                                                                  \
    } while (0)

    // chunk 0 -> regs -> buf0
    GEMM_LOAD(0);
    GEMM_STORE(smg);
    // chunk 1 -> regs
    GEMM_LOAD(64);

    const int bcolw = warpN * 32;

    for (int ch = 0; ch < NCH; ch++) {
        __syncthreads();   // all warps done with iter ch-1

        if (ch + 1 < NCH)
            GEMM_STORE(smg + ((ch + 1) & 1) * G_STAGE);

        if (ch + 2 < NCH)
            GEMM_LOAD((ch + 2) * 64);

        const u32* sA = smg + (ch & 1) * G_STAGE;
        const u32* sB = sA + G_STAGE_A;
        const u32* sAw = sA + (warpM * 64) * G_SA_LD;

        #pragma unroll
        for (int ks = 0; ks < 4; ks++) {
            const int kw = ks * 8;           // A word offset / B kp-row base
            u32 af[4][4], bf[4][2];
            #pragma unroll
            for (int i = 0; i < 4; i++) {
                const u32* base = sAw + (i * 16 + g) * G_SA_LD + kw + tg;
                af[i][0] = base[0];
                af[i][1] = base[8 * G_SA_LD];
                af[i][2] = base[4];
                af[i][3] = base[8 * G_SA_LD + 4];
            }
            #pragma unroll
            for (int j = 0; j < 4; j++) {
                const u32* base = sB + (kw + tg) * G_SB_LD + bcolw + j * 8 + g;
                bf[j][0] = base[0];
                bf[j][1] = base[4 * G_SB_LD];
            }
            #pragma unroll
            for (int i = 0; i < 4; i++)
                #pragma unroll
                for (int j = 0; j < 4; j++)
                    mma_f16(c[i][j], af[i], bf[j]);
        }
    }

    #undef GEMM_LOAD
    #undef GEMM_STORE

    // epilogue
    #pragma unroll
    for (int i = 0; i < 4; i++) {
        const int r0e = row0 + warpM * 64 + i * 16 + g;
        #pragma unroll
        for (int j = 0; j < 4; j++) {
            const int col = col0 + warpN * 32 + j * 8 + 2 * tg;
            float bb0 = 0.f, bb1 = 0.f;
            if (bias) { bb0 = bias[col]; bb1 = bias[col + 1]; }
            *(float2*)(C + (size_t)r0e * Nw + col) =
                make_float2(c[i][j][0] + bb0, c[i][j][1] + bb1);
            *(float2*)(C + (size_t)(r0e + 8) * Nw + col) =
                make_float2(c[i][j][2] + bb0, c[i][j][3] + bb1);
        }
    }
}

// ---------------------------------------------------------------------------
// RoPE in place (round-4 verbatim)
// ---------------------------------------------------------------------------
__global__ void rope_kernel(const float* __restrict__ cosT,
                            const float* __restrict__ sinT,
                            int nheads, int which)
{
    float* X = which ? g_Q : g_K;
    const int idx = blockIdx.x * blockDim.x + threadIdx.x;
    const int total = SEQ * nheads * 64;
    if (idx >= total) return;
    const int d = idx & 63;
    const int h = (idx >> 6) % nheads;
    const int s = idx / (64 * nheads);

    const float c1 = cosT[s * HD + d];
    const float s1 = sinT[s * HD + d];
    const float c2 = cosT[s * HD + d + 64];
    const float s2 = sinT[s * HD + d + 64];

    float* p = X + (size_t)s * (nheads * HD) + h * HD + d;
    const float x1 = p[0];
    const float x2 = p[64];
    p[0]  = x1 * c1 - x2 * s1;
    p[64] = x2 * c2 + x1 * s2;
}

// ---------------------------------------------------------------------------
// Full-fp16 flash attention with double-buffered single-barrier staging
// (round-14 verbatim, proven at 117us).
// ---------------------------------------------------------------------------
#define KLD16 68
#define VLD16 136
#define SK16_WORDS (64*KLD16)                // 4352
#define SVT_WORDS  (32*VLD16)                // 4352
#define A_STG (SK16_WORDS + SVT_WORDS)       // 8704 words per stage
#define ATTN_SMEM (2*A_STG*4)                // 69632 B

__device__ __forceinline__ void attn_stage(
    u32* buf, int kt, int ntiles, int kvh, int t)
{
    u32* bK = buf;
    u32* bV = buf + SK16_WORDS;
    #pragma unroll
    for (int p = 0; p < 16; p++) {
        const int idx = p * 128 + t;
        const int key = idx >> 5;
        const int d4 = (idx & 31) * 4;
        const float4 kk =
            *(const float4*)&g_K[(size_t)(kt * 64 + key) * KVW + kvh * HD + d4];
        *(uint2*)(bK + key * KLD16 + (d4 >> 1)) =
            make_uint2(pack_h2(kk.x, kk.y), pack_h2(kk.z, kk.w));
    }
    #pragma unroll
    for (int p = 0; p < 8; p++) {
        const int idx = p * 128 + t;
        const int kp = idx >> 5;
        const int d4 = (idx & 31) * 4;
        const size_t base = (size_t)(kt * 64 + 2 * kp) * KVW + kvh * HD + d4;
        const float4 v0 = *(const float4*)&g_V[base];
        const float4 v1 = *(const float4*)&g_V[base + KVW];
        *(uint4*)(bV + kp * VLD16 + d4) = make_uint4(
            pack_h2(v0.x, v1.x), pack_h2(v0.y, v1.y),
            pack_h2(v0.z, v1.z), pack_h2(v0.w, v1.w));
    }
    if (kt + 1 < ntiles) {
        #pragma unroll
        for (int q2 = 0; q2 < 2; q2++) {
            const int li = t * 2 + q2;
            const int row = li >> 2, seg = li & 3;
            const char* ka = (const char*)
                &g_K[(size_t)((kt + 1) * 64 + row) * KVW + kvh * HD] + seg * 128;
            const char* va = (const char*)
                &g_V[(size_t)((kt + 1) * 64 + row) * KVW + kvh * HD] + seg * 128;
            prefetch_l1(ka);
            prefetch_l1(va);
        }
    }
}

__global__ void __launch_bounds__(128) attn_mma_kernel()
{
    extern __shared__ u32 smem[];

    const int t = threadIdx.x;
    const int lane = t & 31, wid = t >> 5;
    const int g = lane >> 2, tg = lane & 3;
    const int qt = 31 - blockIdx.x;          // heavy tiles first
    const int h  = blockIdx.y;
    const int kvh = h >> 3;
    const int qbase = qt * 64 + wid * 16;
    const int r0 = qbase + g, r1 = qbase + g + 8;

    u32 qf[8][4];
    const float* Qp = g_Q + (size_t)qbase * HIDDEN + h * HD;
    #pragma unroll
    for (int ks = 0; ks < 8; ks++) {
        const float2 a0 = *(const float2*)(Qp + (size_t)g * HIDDEN + ks * 16 + 2 * tg);
        const float2 a1 = *(const float2*)(Qp + (size_t)(g + 8) * HIDDEN + ks * 16 + 2 * tg);
        const float2 a2 = *(const float2*)(Qp + (size_t)g * HIDDEN + ks * 16 + 8 + 2 * tg);
        const float2 a3 = *(const float2*)(Qp + (size_t)(g + 8) * HIDDEN + ks * 16 + 8 + 2 * tg);
        qf[ks][0] = pack_h2(a0.x, a0.y);
        qf[ks][1] = pack_h2(a1.x, a1.y);
        qf[ks][2] = pack_h2(a2.x, a2.y);
        qf[ks][3] = pack_h2(a3.x, a3.y);
    }

    float o[16][4];
    #pragma unroll
    for (int n = 0; n < 16; n++)
        #pragma unroll
        for (int r = 0; r < 4; r++) o[n][r] = 0.f;
    float m0 = -1e30f, m1 = -1e30f, l0 = 0.f, l1 = 0.f;

    const int ntiles = qt + 1;

    attn_stage(smem, 0, ntiles, kvh, t);
    __syncthreads();

    for (int kt = 0; kt < ntiles; kt++) {
        const u32* sK16 = smem + (kt & 1) * A_STG;
        const u32* sVT  = sK16 + SK16_WORDS;

        if (kt * 64 <= qbase + 15) {
            float c[8][4];
            #pragma unroll
            for (int j = 0; j < 8; j++)
                #pragma unroll
                for (int r = 0; r < 4; r++) c[j][r] = 0.f;

            #pragma unroll
            for (int ks = 0; ks < 8; ks++) {
                #pragma unroll
                for (int j = 0; j < 8; j++) {
                    u32 bf[2];
                    const u32* bb = sK16 + (j * 8 + g) * KLD16 + ks * 8 + tg;
                    bf[0] = bb[0];
                    bf[1] = bb[4];
                    mma_f16(c[j], qf[ks], bf);
                }
            }

            const bool diag = (kt * 64 + 63 > qbase);
            #pragma unroll
            for (int j = 0; j < 8; j++) {
                const int key = kt * 64 + j * 8 + 2 * tg;
                c[j][0] *= ATT_SCALE; c[j][1] *= ATT_SCALE;
                c[j][2] *= ATT_SCALE; c[j][3] *= ATT_SCALE;
                if (diag) {
                    if (key     > r0) c[j][0] = -1e30f;
                    if (key + 1 > r0) c[j][1] = -1e30f;
                    if (key     > r1) c[j][2] = -1e30f;
                    if (key + 1 > r1) c[j][3] = -1e30f;
                }
            }

            float mx0 = m0, mx1 = m1;
            #pragma unroll
            for (int j = 0; j < 8; j++) {
                mx0 = fmaxf(mx0, fmaxf(c[j][0], c[j][1]));
                mx1 = fmaxf(mx1, fmaxf(c[j][2], c[j][3]));
            }
            mx0 = fmaxf(mx0, __shfl_xor_sync(0xffffffffu, mx0, 1));
            mx0 = fmaxf(mx0, __shfl_xor_sync(0xffffffffu, mx0, 2));
            mx1 = fmaxf(mx1, __shfl_xor_sync(0xffffffffu, mx1, 1));
            mx1 = fmaxf(mx1, __shfl_xor_sync(0xffffffffu, mx1, 2));
            const float corr0 = __expf(m0 - mx0);
            const float corr1 = __expf(m1 - mx1);
            m0 = mx0; m1 = mx1;
            l0 *= corr0; l1 *= corr1;
            #pragma unroll
            for (int n = 0; n < 16; n++) {
                o[n][0] *= corr0; o[n][1] *= corr0;
                o[n][2] *= corr1; o[n][3] *= corr1;
            }

            float s0 = 0.f, s1 = 0.f;
            #pragma unroll
            for (int kg = 0; kg < 4; kg++) {
                const int j0 = kg * 2, j1 = kg * 2 + 1;
                const float e00a = __expf(c[j0][0] - m0);
                const float e01a = __expf(c[j0][1] - m0);
                const float e10a = __expf(c[j0][2] - m1);
                const float e11a = __expf(c[j0][3] - m1);
                const float e00b = __expf(c[j1][0] - m0);
                const float e01b = __expf(c[j1][1] - m0);
                const float e10b = __expf(c[j1][2] - m1);
                const float e11b = __expf(c[j1][3] - m1);
                s0 += e00a + e01a + e00b + e01b;
                s1 += e10a + e11a + e10b + e11b;

                u32 af[4];
                af[0] = pack_h2(e00a, e01a);
                af[1] = pack_h2(e10a, e11a);
                af[2] = pack_h2(e00b, e01b);
                af[3] = pack_h2(e10b, e11b);

                #pragma unroll
                for (int n = 0; n < 16; n++) {
                    u32 bf[2];
                    const u32* bb = sVT + (kg * 8 + tg) * VLD16 + n * 8 + g;
                    bf[0] = bb[0];
                    bf[1] = bb[4 * VLD16];
                    mma_f16(o[n], af, bf);
                }
            }
            s0 += __shfl_xor_sync(0xffffffffu, s0, 1);
            s0 += __shfl_xor_sync(0xffffffffu, s0, 2);
            s1 += __shfl_xor_sync(0xffffffffu, s1, 1);
            s1 += __shfl_xor_sync(0xffffffffu, s1, 2);
            l0 += s0; l1 += s1;
        }

        if (kt + 1 < ntiles)
            attn_stage(smem + ((kt + 1) & 1) * A_STG, kt + 1, ntiles, kvh, t);

        __syncthreads();
    }

    const float inv0 = 1.f / l0;
    const float inv1 = 1.f / l1;
    float* cp0 = g_C + (size_t)r0 * HIDDEN + h * HD;
    float* cp1 = g_C + (size_t)r1 * HIDDEN + h * HD;
    #pragma unroll
    for (int n = 0; n < 16; n++) {
        const int col = n * 8 + 2 * tg;
        *(float2*)(cp0 + col) = make_float2(o[n][0] * inv0, o[n][1] * inv0);
        *(float2*)(cp1 + col) = make_float2(o[n][2] * inv1, o[n][3] * inv1);
    }
}

// ---------------------------------------------------------------------------
extern "C" void kernel_launch(void* const* d_in, const int* in_sizes, int n_in,
                              void* d_out, int out_size)
{
    const float* hs   = (const float*)d_in[0];
    const float* cosT = (const float*)d_in[1];
    const float* sinT = (const float*)d_in[2];
    // d_in[3] = attention_mask (pure causal; applied analytically)
    const float* Wq = (const float*)d_in[4];
    const float* bq = (const float*)d_in[5];
    const float* Wk = (const float*)d_in[6];
    const float* bk = (const float*)d_in[7];
    const float* Wv = (const float*)d_in[8];
    const float* bv = (const float*)d_in[9];
    const float* Wo = (const float*)d_in[10];
    float* out = (float*)d_out;

    cudaFuncSetAttribute(mma_gemm_kernel,
                         cudaFuncAttributeMaxDynamicSharedMemorySize, G_SMEM);
    cudaFuncSetAttribute(attn_mma_kernel,
                         cudaFuncAttributeMaxDynamicSharedMemorySize, ATTN_SMEM);

    // fused QKV projection: blocks 0-15 -> Q, 16-17 -> K, 18-19 -> V
    mma_gemm_kernel<<<dim3(20, 16), 256, G_SMEM>>>(
        hs, Wq, Wk, Wv, bq, bk, bv, nullptr, 1);

    rope_kernel<<<(SEQ * NH  * 64 + 255) / 256, 256>>>(cosT, sinT, NH, 1);
    rope_kernel<<<(SEQ * NKV * 64 + 255) / 256, 256>>>(cosT, sinT, NKV, 0);

    attn_mma_kernel<<<dim3(32, 16), 128, ATTN_SMEM>>>();

    // O projection
    mma_gemm_kernel<<<dim3(16, 16), 256, G_SMEM>>>(
        g_C, Wo, nullptr, nullptr, nullptr, nullptr, nullptr, out, 0);
}

// round 16
// speedup vs baseline: 1.4506x; 1.4506x over previous
#include <cuda_runtime.h>

typedef unsigned int u32;

#define SEQ 2048
#define HIDDEN 2048
#define NH 16
#define NKV 2
#define HD 128
#define KVW (NKV*HD)          // 256
#define ATT_SCALE 0.08838834764831845f

// ---------------- scratch (no allocations allowed) ----------------
__device__ float g_Q[SEQ*HIDDEN];
__device__ float g_K[SEQ*KVW];
__device__ float g_V[SEQ*KVW];
__device__ u32   g_C16[SEQ*(HIDDEN/2)];   // attention out, half2-packed along d

// ---------------- helpers ----------------
__device__ __forceinline__ void mma_f16(float* c, const u32* a, const u32* b) {
    asm volatile(
        "mma.sync.aligned.m16n8k16.row.col.f32.f16.f16.f32 "
        "{%0,%1,%2,%3}, {%4,%5,%6,%7}, {%8,%9}, {%0,%1,%2,%3};"
        : "+f"(c[0]), "+f"(c[1]), "+f"(c[2]), "+f"(c[3])
        : "r"(a[0]), "r"(a[1]), "r"(a[2]), "r"(a[3]),
          "r"(b[0]), "r"(b[1]));
}
// pack two fp32 -> f16x2, 'lo' in low half (convention verified R10-R14)
__device__ __forceinline__ u32 pack_h2(float lo, float hi) {
    u32 r;
    asm("cvt.rn.f16x2.f32 %0, %1, %2;" : "=r"(r) : "f"(hi), "f"(lo));
    return r;
}
__device__ __forceinline__ void prefetch_l1(const void* p) {
    asm volatile("prefetch.global.L1 [%0];" :: "l"(p));
}

// ---------------------------------------------------------------------------
// fp16 mma.sync GEMM (R11/R14 proven): 128x128 tile, 8 warps (2Mx4N),
// K-chunk 32 (2 ksteps of m16n8k16), double-buffered smem, reg staging.
// mode 1: fused QKV from fp32 hs (blocks 0-15 -> Q, 16-17 -> K, 18-19 -> V)
// mode 0: O-proj; A read as PRE-PACKED fp16 (g_C16) -> staging is raw copy.
// ---------------------------------------------------------------------------
#define G_SA_LD 20
#define G_SB_LD 136
#define G_STAGE_A (128*G_SA_LD)              // 2560 words
#define G_STAGE (G_STAGE_A + 16*G_SB_LD)     // 4736 words
#define G_SMEM (2*G_STAGE*4)                 // 37888 B

__global__ void __launch_bounds__(256) mma_gemm_kernel(
    const float* __restrict__ A_ext,
    const float* __restrict__ W0, const float* __restrict__ W1,
    const float* __restrict__ W2,
    const float* __restrict__ b0, const float* __restrict__ b1,
    const float* __restrict__ b2,
    float* __restrict__ outF, int mode)
{
    extern __shared__ u32 smg[];
    const int t = threadIdx.x;
    const int wid = t >> 5, lane = t & 31;
    const int warpM = wid & 1, warpN = wid >> 1;
    const int g = lane >> 2, tg = lane & 3;
    const int row0 = blockIdx.y * 128;

    const float* A; const float* W; const float* bias; float* C; int Nw; int col0;
    if (mode == 1) {
        A = A_ext;
        const int bn = blockIdx.x;
        if (bn < 16)      { W = W0; bias = b0; C = g_Q; Nw = HIDDEN; col0 = bn * 128; }
        else if (bn < 18) { W = W1; bias = b1; C = g_K; Nw = KVW;    col0 = (bn - 16) * 128; }
        else              { W = W2; bias = b2; C = g_V; Nw = KVW;    col0 = (bn - 18) * 128; }
    } else {
        A = nullptr; W = W0; bias = nullptr; C = outF; Nw = HIDDEN; col0 = blockIdx.x * 128;
    }

    float c[4][4][4];
    #pragma unroll
    for (int i = 0; i < 4; i++)
        #pragma unroll
        for (int j = 0; j < 4; j++)
            #pragma unroll
            for (int r = 0; r < 4; r++) c[i][j][r] = 0.f;

    const int arow = t >> 3;           // 0..31 (4 passes of +32)
    const int aseg = t & 7;            // k-quad within 32-k chunk
    const int bkp  = t >> 6;           // 0..3  (4 passes of +4 k-pairs)
    const int bcol = (t & 63) * 2;

    const float* Ap  = (mode == 1) ? A + (size_t)(row0 + arow) * HIDDEN + aseg * 4 : nullptr;
    const u32*  Ap16 = (mode == 0) ? g_C16 + (size_t)(row0 + arow) * (HIDDEN/2) + aseg * 2 : nullptr;
    const float* Bp0 = W + (size_t)(2 * bkp) * Nw + col0 + bcol;
    const float* Bp1 = Bp0 + Nw;
    const size_t aRow32   = (size_t)32 * HIDDEN;
    const size_t aRow32h  = (size_t)32 * (HIDDEN/2);
    const size_t bRow8    = (size_t)8 * Nw;
    const int NCH = HIDDEN >> 5;

    float4 ar[4]; uint2 ar16[4]; float2 br0[4], br1[4];

    #define GEMM_LOAD(ko) do {                                              \
        _Pragma("unroll")                                                   \
        for (int p = 0; p < 4; p++) {                                       \
            if (mode == 1) ar[p] = *(const float4*)(Ap + (ko) + p * aRow32);\
            else ar16[p] = *(const uint2*)(Ap16 + ((ko) >> 1) + p * aRow32h);\
            br0[p] = *(const float2*)(Bp0 + (size_t)(ko) * Nw + p * bRow8); \
            br1[p] = *(const float2*)(Bp1 + (size_t)(ko) * Nw + p * bRow8); \
        }                                                                   \
    } while (0)

    #define GEMM_STORE(buf) do {                                            \
        _Pragma("unroll")                                                   \
        for (int p = 0; p < 4; p++) {                                       \
            uint2 aw = (mode == 1)                                          \
                ? make_uint2(pack_h2(ar[p].x, ar[p].y),                     \
                             pack_h2(ar[p].z, ar[p].w))                     \
                : ar16[p];                                                  \
            *(uint2*)((buf) + (arow + p * 32) * G_SA_LD + aseg * 2) = aw;   \
            *(uint2*)((buf) + G_STAGE_A + (bkp + p * 4) * G_SB_LD + bcol) = \
                make_uint2(pack_h2(br0[p].x, br1[p].x),                     \
                           pack_h2(br0[p].y, br1[p].y));                    \
        }                                                                   \
    } while (0)

    GEMM_LOAD(0);
    GEMM_STORE(smg);
    GEMM_LOAD(32);

    const int bcolw = warpN * 32;

    for (int ch = 0; ch < NCH; ch++) {
        __syncthreads();   // all warps done with iter ch-1

        if (ch + 1 < NCH)
            GEMM_STORE(smg + ((ch + 1) & 1) * G_STAGE);

        if (ch + 2 < NCH)
            GEMM_LOAD((ch + 2) * 32);

        const u32* sA = smg + (ch & 1) * G_STAGE;
        const u32* sB = sA + G_STAGE_A;
        const u32* sAw = sA + (warpM * 64) * G_SA_LD;

        #pragma unroll
        for (int ks = 0; ks < 2; ks++) {
            const int kw = ks * 8;
            u32 af[4][4], bf[4][2];
            #pragma unroll
            for (int i = 0; i < 4; i++) {
                const u32* base = sAw + (i * 16 + g) * G_SA_LD + kw + tg;
                af[i][0] = base[0];
                af[i][1] = base[8 * G_SA_LD];
                af[i][2] = base[4];
                af[i][3] = base[8 * G_SA_LD + 4];
            }
            #pragma unroll
            for (int j = 0; j < 4; j++) {
                const u32* base = sB + (kw + tg) * G_SB_LD + bcolw + j * 8 + g;
                bf[j][0] = base[0];
                bf[j][1] = base[4 * G_SB_LD];
            }
            #pragma unroll
            for (int i = 0; i < 4; i++)
                #pragma unroll
                for (int j = 0; j < 4; j++)
                    mma_f16(c[i][j], af[i], bf[j]);
        }
    }

    #undef GEMM_LOAD
    #undef GEMM_STORE

    #pragma unroll
    for (int i = 0; i < 4; i++) {
        const int r0e = row0 + warpM * 64 + i * 16 + g;
        #pragma unroll
        for (int j = 0; j < 4; j++) {
            const int col = col0 + warpN * 32 + j * 8 + 2 * tg;
            float bb0 = 0.f, bb1 = 0.f;
            if (bias) { bb0 = bias[col]; bb1 = bias[col + 1]; }
            *(float2*)(C + (size_t)r0e * Nw + col) =
                make_float2(c[i][j][0] + bb0, c[i][j][1] + bb1);
            *(float2*)(C + (size_t)(r0e + 8) * Nw + col) =
                make_float2(c[i][j][2] + bb0, c[i][j][3] + bb1);
        }
    }
}

// ---------------------------------------------------------------------------
// RoPE: fused Q+K, float4-vectorized (identical per-element math to R4 rope)
// ---------------------------------------------------------------------------
#define ROPE_QN (SEQ*NH*16)
#define ROPE_KN (SEQ*NKV*16)

__global__ void rope_kernel(const float* __restrict__ cosT,
                            const float* __restrict__ sinT)
{
    const int idx = blockIdx.x * blockDim.x + threadIdx.x;
    float* X; int nheads; int li;
    if (idx < ROPE_QN)                { X = g_Q; nheads = NH;  li = idx; }
    else if (idx < ROPE_QN + ROPE_KN) { X = g_K; nheads = NKV; li = idx - ROPE_QN; }
    else return;

    const int d4 = (li & 15) * 4;
    const int h = (li >> 4) % nheads;
    const int s = li / (16 * nheads);

    const float4 c1 = *(const float4*)&cosT[s * HD + d4];
    const float4 s1 = *(const float4*)&sinT[s * HD + d4];
    const float4 c2 = *(const float4*)&cosT[s * HD + d4 + 64];
    const float4 s2 = *(const float4*)&sinT[s * HD + d4 + 64];

    float4* p = (float4*)(X + (size_t)s * (nheads * HD) + h * HD + d4);
    const float4 x1 = p[0];
    const float4 x2 = p[16];   // +64 floats

    float4 y1, y2;
    y1.x = x1.x * c1.x - x2.x * s1.x;
    y1.y = x1.y * c1.y - x2.y * s1.y;
    y1.z = x1.z * c1.z - x2.z * s1.z;
    y1.w = x1.w * c1.w - x2.w * s1.w;
    y2.x = x2.x * c2.x + x1.x * s2.x;
    y2.y = x2.y * c2.y + x1.y * s2.y;
    y2.z = x2.z * c2.z + x1.z * s2.z;
    y2.w = x2.w * c2.w + x1.w * s2.w;
    p[0]  = y1;
    p[16] = y2;
}

// ---------------------------------------------------------------------------
// Full-fp16 flash attention, double-buffered single-barrier staging
// (R14 verbatim except epilogue now packs fp16 into g_C16 — bit-identical
// values to what the O-proj staging would have produced).
// ---------------------------------------------------------------------------
#define KLD16 68
#define VLD16 136
#define SK16_WORDS (64*KLD16)                // 4352
#define SVT_WORDS  (32*VLD16)                // 4352
#define A_STG (SK16_WORDS + SVT_WORDS)       // 8704 words per stage
#define ATTN_SMEM (2*A_STG*4)                // 69632 B

__device__ __forceinline__ void attn_stage(
    u32* buf, int kt, int ntiles, int kvh, int t)
{
    u32* bK = buf;
    u32* bV = buf + SK16_WORDS;
    #pragma unroll
    for (int p = 0; p < 16; p++) {
        const int idx = p * 128 + t;
        const int key = idx >> 5;
        const int d4 = (idx & 31) * 4;
        const float4 kk =
            *(const float4*)&g_K[(size_t)(kt * 64 + key) * KVW + kvh * HD + d4];
        *(uint2*)(bK + key * KLD16 + (d4 >> 1)) =
            make_uint2(pack_h2(kk.x, kk.y), pack_h2(kk.z, kk.w));
    }
    #pragma unroll
    for (int p = 0; p < 8; p++) {
        const int idx = p * 128 + t;
        const int kp = idx >> 5;
        const int d4 = (idx & 31) * 4;
        const size_t base = (size_t)(kt * 64 + 2 * kp) * KVW + kvh * HD + d4;
        const float4 v0 = *(const float4*)&g_V[base];
        const float4 v1 = *(const float4*)&g_V[base + KVW];
        *(uint4*)(bV + kp * VLD16 + d4) = make_uint4(
            pack_h2(v0.x, v1.x), pack_h2(v0.y, v1.y),
            pack_h2(v0.z, v1.z), pack_h2(v0.w, v1.w));
    }
    if (kt + 1 < ntiles) {
        #pragma unroll
        for (int q2 = 0; q2 < 2; q2++) {
            const int li = t * 2 + q2;
            const int row = li >> 2, seg = li & 3;
            const char* ka = (const char*)
                &g_K[(size_t)((kt + 1) * 64 + row) * KVW + kvh * HD] + seg * 128;
            const char* va = (const char*)
                &g_V[(size_t)((kt + 1) * 64 + row) * KVW + kvh * HD] + seg * 128;
            prefetch_l1(ka);
            prefetch_l1(va);
        }
    }
}

__global__ void __launch_bounds__(128) attn_mma_kernel()
{
    extern __shared__ u32 smem[];

    const int t = threadIdx.x;
    const int lane = t & 31, wid = t >> 5;
    const int g = lane >> 2, tg = lane & 3;
    const int qt = 31 - blockIdx.x;          // heavy tiles first
    const int h  = blockIdx.y;
    const int kvh = h >> 3;
    const int qbase = qt * 64 + wid * 16;
    const int r0 = qbase + g, r1 = qbase + g + 8;

    u32 qf[8][4];
    const float* Qp = g_Q + (size_t)qbase * HIDDEN + h * HD;
    #pragma unroll
    for (int ks = 0; ks < 8; ks++) {
        const float2 a0 = *(const float2*)(Qp + (size_t)g * HIDDEN + ks * 16 + 2 * tg);
        const float2 a1 = *(const float2*)(Qp + (size_t)(g + 8) * HIDDEN + ks * 16 + 2 * tg);
        const float2 a2 = *(const float2*)(Qp + (size_t)g * HIDDEN + ks * 16 + 8 + 2 * tg);
        const float2 a3 = *(const float2*)(Qp + (size_t)(g + 8) * HIDDEN + ks * 16 + 8 + 2 * tg);
        qf[ks][0] = pack_h2(a0.x, a0.y);
        qf[ks][1] = pack_h2(a1.x, a1.y);
        qf[ks][2] = pack_h2(a2.x, a2.y);
        qf[ks][3] = pack_h2(a3.x, a3.y);
    }

    float o[16][4];
    #pragma unroll
    for (int n = 0; n < 16; n++)
        #pragma unroll
        for (int r = 0; r < 4; r++) o[n][r] = 0.f;
    float m0 = -1e30f, m1 = -1e30f, l0 = 0.f, l1 = 0.f;

    const int ntiles = qt + 1;

    attn_stage(smem, 0, ntiles, kvh, t);
    __syncthreads();

    for (int kt = 0; kt < ntiles; kt++) {
        const u32* sK16 = smem + (kt & 1) * A_STG;
        const u32* sVT  = sK16 + SK16_WORDS;

        if (kt * 64 <= qbase + 15) {
            float c[8][4];
            #pragma unroll
            for (int j = 0; j < 8; j++)
                #pragma unroll
                for (int r = 0; r < 4; r++) c[j][r] = 0.f;

            #pragma unroll
            for (int ks = 0; ks < 8; ks++) {
                #pragma unroll
                for (int j = 0; j < 8; j++) {
                    u32 bf[2];
                    const u32* bb = sK16 + (j * 8 + g) * KLD16 + ks * 8 + tg;
                    bf[0] = bb[0];
                    bf[1] = bb[4];
                    mma_f16(c[j], qf[ks], bf);
                }
            }

            const bool diag = (kt * 64 + 63 > qbase);
            #pragma unroll
            for (int j = 0; j < 8; j++) {
                const int key = kt * 64 + j * 8 + 2 * tg;
                c[j][0] *= ATT_SCALE; c[j][1] *= ATT_SCALE;
                c[j][2] *= ATT_SCALE; c[j][3] *= ATT_SCALE;
                if (diag) {
                    if (key     > r0) c[j][0] = -1e30f;
                    if (key + 1 > r0) c[j][1] = -1e30f;
                    if (key     > r1) c[j][2] = -1e30f;
                    if (key + 1 > r1) c[j][3] = -1e30f;
                }
            }

            float mx0 = m0, mx1 = m1;
            #pragma unroll
            for (int j = 0; j < 8; j++) {
                mx0 = fmaxf(mx0, fmaxf(c[j][0], c[j][1]));
                mx1 = fmaxf(mx1, fmaxf(c[j][2], c[j][3]));
            }
            mx0 = fmaxf(mx0, __shfl_xor_sync(0xffffffffu, mx0, 1));
            mx0 = fmaxf(mx0, __shfl_xor_sync(0xffffffffu, mx0, 2));
            mx1 = fmaxf(mx1, __shfl_xor_sync(0xffffffffu, mx1, 1));
            mx1 = fmaxf(mx1, __shfl_xor_sync(0xffffffffu, mx1, 2));
            const float corr0 = __expf(m0 - mx0);
            const float corr1 = __expf(m1 - mx1);
            m0 = mx0; m1 = mx1;
            l0 *= corr0; l1 *= corr1;
            #pragma unroll
            for (int n = 0; n < 16; n++) {
                o[n][0] *= corr0; o[n][1] *= corr0;
                o[n][2] *= corr1; o[n][3] *= corr1;
            }

            float s0 = 0.f, s1 = 0.f;
            #pragma unroll
            for (int kg = 0; kg < 4; kg++) {
                const int j0 = kg * 2, j1 = kg * 2 + 1;
                const float e00a = __expf(c[j0][0] - m0);
                const float e01a = __expf(c[j0][1] - m0);
                const float e10a = __expf(c[j0][2] - m1);
                const float e11a = __expf(c[j0][3] - m1);
                const float e00b = __expf(c[j1][0] - m0);
                const float e01b = __expf(c[j1][1] - m0);
                const float e10b = __expf(c[j1][2] - m1);
                const float e11b = __expf(c[j1][3] - m1);
                s0 += e00a + e01a + e00b + e01b;
                s1 += e10a + e11a + e10b + e11b;

                u32 af[4];
                af[0] = pack_h2(e00a, e01a);
                af[1] = pack_h2(e10a, e11a);
                af[2] = pack_h2(e00b, e01b);
                af[3] = pack_h2(e10b, e11b);

                #pragma unroll
                for (int n = 0; n < 16; n++) {
                    u32 bf[2];
                    const u32* bb = sVT + (kg * 8 + tg) * VLD16 + n * 8 + g;
                    bf[0] = bb[0];
                    bf[1] = bb[4 * VLD16];
                    mma_f16(o[n], af, bf);
                }
            }
            s0 += __shfl_xor_sync(0xffffffffu, s0, 1);
            s0 += __shfl_xor_sync(0xffffffffu, s0, 2);
            s1 += __shfl_xor_sync(0xffffffffu, s1, 1);
            s1 += __shfl_xor_sync(0xffffffffu, s1, 2);
            l0 += s0; l1 += s1;
        }

        if (kt + 1 < ntiles)
            attn_stage(smem + ((kt + 1) & 1) * A_STG, kt + 1, ntiles, kvh, t);

        __syncthreads();
    }

    // ---- epilogue: pack fp16 directly (bit-identical to O-proj staging pack) ----
    const float inv0 = 1.f / l0;
    const float inv1 = 1.f / l1;
    u32* cp0 = g_C16 + (size_t)r0 * (HIDDEN/2) + h * (HD/2);
    u32* cp1 = g_C16 + (size_t)r1 * (HIDDEN/2) + h * (HD/2);
    #pragma unroll
    for (int n = 0; n < 16; n++) {
        const int w = n * 4 + tg;    // word index = (n*8 + 2tg)/2
        cp0[w] = pack_h2(o[n][0] * inv0, o[n][1] * inv0);
        cp1[w] = pack_h2(o[n][2] * inv1, o[n][3] * inv1);
    }
}

// ---------------------------------------------------------------------------
extern "C" void kernel_launch(void* const* d_in, const int* in_sizes, int n_in,
                              void* d_out, int out_size)
{
    const float* hs   = (const float*)d_in[0];
    const float* cosT = (const float*)d_in[1];
    const float* sinT = (const float*)d_in[2];
    // d_in[3] = attention_mask (pure causal; applied analytically)
    const float* Wq = (const float*)d_in[4];
    const float* bq = (const float*)d_in[5];
    const float* Wk = (const float*)d_in[6];
    const float* bk = (const float*)d_in[7];
    const float* Wv = (const float*)d_in[8];
    const float* bv = (const float*)d_in[9];
    const float* Wo = (const float*)d_in[10];
    float* out = (float*)d_out;

    cudaFuncSetAttribute(mma_gemm_kernel,
                         cudaFuncAttributeMaxDynamicSharedMemorySize, G_SMEM);
    cudaFuncSetAttribute(attn_mma_kernel,
                         cudaFuncAttributeMaxDynamicSharedMemorySize, ATTN_SMEM);

    // fused QKV projection: blocks 0-15 -> Q, 16-17 -> K, 18-19 -> V
    mma_gemm_kernel<<<dim3(20, 16), 256, G_SMEM>>>(
        hs, Wq, Wk, Wv, bq, bk, bv, nullptr, 1);

    // fused vectorized RoPE (Q + K)
    rope_kernel<<<(ROPE_QN + ROPE_KN + 255) / 256, 256>>>(cosT, sinT);

    attn_mma_kernel<<<dim3(32, 16), 128, ATTN_SMEM>>>();

    // O projection (A = pre-packed fp16 g_C16)
    mma_gemm_kernel<<<dim3(16, 16), 256, G_SMEM>>>(
        nullptr, Wo, nullptr, nullptr, nullptr, nullptr, nullptr, out, 0);
}

// round 17
// speedup vs baseline: 1.6277x; 1.1221x over previous
#include <cuda_runtime.h>

typedef unsigned int u32;

#define SEQ 2048
#define HIDDEN 2048
#define NH 16
#define NKV 2
#define HD 128
#define KVW (NKV*HD)          // 256
#define ATT_SCALE 0.08838834764831845f

// ---------------- scratch (no allocations allowed) ----------------
__device__ float g_Q[SEQ*HIDDEN];
__device__ float g_K[SEQ*KVW];
__device__ float g_V[SEQ*KVW];
__device__ float g_C[SEQ*HIDDEN];

// ---------------- helpers ----------------
__device__ __forceinline__ void mma_f16(float* c, const u32* a, const u32* b) {
    asm volatile(
        "mma.sync.aligned.m16n8k16.row.col.f32.f16.f16.f32 "
        "{%0,%1,%2,%3}, {%4,%5,%6,%7}, {%8,%9}, {%0,%1,%2,%3};"
        : "+f"(c[0]), "+f"(c[1]), "+f"(c[2]), "+f"(c[3])
        : "r"(a[0]), "r"(a[1]), "r"(a[2]), "r"(a[3]),
          "r"(b[0]), "r"(b[1]));
}
// pack two fp32 -> f16x2, 'lo' in low half (convention verified R10-R14)
__device__ __forceinline__ u32 pack_h2(float lo, float hi) {
    u32 r;
    asm("cvt.rn.f16x2.f32 %0, %1, %2;" : "=r"(r) : "f"(hi), "f"(lo));
    return r;
}
__device__ __forceinline__ void prefetch_l1(const void* p) {
    asm volatile("prefetch.global.L1 [%0];" :: "l"(p));
}

// ---------------------------------------------------------------------------
// fp16 mma.sync GEMM (R11/R14 proven): 128x128 tile, 8 warps (2Mx4N),
// K-chunk 32 (2 ksteps of m16n8k16), double-buffered smem, reg staging.
// mode 1: fused QKV (blocks 0-15 -> Q, 16-17 -> K, 18-19 -> V), mode 0: O-proj.
// ---------------------------------------------------------------------------
#define G_SA_LD 20
#define G_SB_LD 136
#define G_STAGE_A (128*G_SA_LD)              // 2560 words
#define G_STAGE (G_STAGE_A + 16*G_SB_LD)     // 4736 words
#define G_SMEM (2*G_STAGE*4)                 // 37888 B

__device__ __forceinline__ void gemm_stage_store(
    u32* buf, const float4* ar, const float2* br0, const float2* br1,
    int arow, int aseg, int bkp, int bcol)
{
    #pragma unroll
    for (int p = 0; p < 4; p++) {
        *(uint2*)(buf + (arow + p * 32) * G_SA_LD + aseg * 2) =
            make_uint2(pack_h2(ar[p].x, ar[p].y), pack_h2(ar[p].z, ar[p].w));
        *(uint2*)(buf + G_STAGE_A + (bkp + p * 4) * G_SB_LD + bcol) =
            make_uint2(pack_h2(br0[p].x, br1[p].x), pack_h2(br0[p].y, br1[p].y));
    }
}

__global__ void __launch_bounds__(256) mma_gemm_kernel(
    const float* __restrict__ A_ext,
    const float* __restrict__ W0, const float* __restrict__ W1,
    const float* __restrict__ W2,
    const float* __restrict__ b0, const float* __restrict__ b1,
    const float* __restrict__ b2,
    float* __restrict__ outF, int mode)
{
    extern __shared__ u32 smg[];
    const int t = threadIdx.x;
    const int wid = t >> 5, lane = t & 31;
    const int warpM = wid & 1, warpN = wid >> 1;
    const int g = lane >> 2, tg = lane & 3;
    const int row0 = blockIdx.y * 128;

    const float* A; const float* W; const float* bias; float* C; int Nw; int col0;
    if (mode == 1) {
        A = A_ext;
        const int bn = blockIdx.x;
        if (bn < 16)      { W = W0; bias = b0; C = g_Q; Nw = HIDDEN; col0 = bn * 128; }
        else if (bn < 18) { W = W1; bias = b1; C = g_K; Nw = KVW;    col0 = (bn - 16) * 128; }
        else              { W = W2; bias = b2; C = g_V; Nw = KVW;    col0 = (bn - 18) * 128; }
    } else {
        A = g_C; W = W0; bias = nullptr; C = outF; Nw = HIDDEN; col0 = blockIdx.x * 128;
    }

    float c[4][4][4];
    #pragma unroll
    for (int i = 0; i < 4; i++)
        #pragma unroll
        for (int j = 0; j < 4; j++)
            #pragma unroll
            for (int r = 0; r < 4; r++) c[i][j][r] = 0.f;

    const int arow = t >> 3;
    const int aseg = t & 7;
    const int bkp  = t >> 6;
    const int bcol = (t & 63) * 2;

    const float* Ap  = A + (size_t)(row0 + arow) * HIDDEN + aseg * 4;
    const float* Bp0 = W + (size_t)(2 * bkp) * Nw + col0 + bcol;
    const float* Bp1 = Bp0 + Nw;
    const size_t aRow32 = (size_t)32 * HIDDEN;
    const size_t bRow8  = (size_t)8 * Nw;
    const int NCH = HIDDEN >> 5;

    float4 ar[4]; float2 br0[4], br1[4];
    #pragma unroll
    for (int p = 0; p < 4; p++) {
        ar[p]  = *(const float4*)(Ap + p * aRow32);
        br0[p] = *(const float2*)(Bp0 + p * bRow8);
        br1[p] = *(const float2*)(Bp1 + p * bRow8);
    }
    gemm_stage_store(smg, ar, br0, br1, arow, aseg, bkp, bcol);
    #pragma unroll
    for (int p = 0; p < 4; p++) {
        ar[p]  = *(const float4*)(Ap + 32 + p * aRow32);
        br0[p] = *(const float2*)(Bp0 + (size_t)32 * Nw + p * bRow8);
        br1[p] = *(const float2*)(Bp1 + (size_t)32 * Nw + p * bRow8);
    }

    const int bcolw = warpN * 32;

    for (int ch = 0; ch < NCH; ch++) {
        __syncthreads();

        if (ch + 1 < NCH)
            gemm_stage_store(smg + ((ch + 1) & 1) * G_STAGE, ar, br0, br1,
                             arow, aseg, bkp, bcol);

        if (ch + 2 < NCH) {
            const int ko = (ch + 2) * 32;
            #pragma unroll
            for (int p = 0; p < 4; p++) {
                ar[p]  = *(const float4*)(Ap + ko + p * aRow32);
                br0[p] = *(const float2*)(Bp0 + (size_t)ko * Nw + p * bRow8);
                br1[p] = *(const float2*)(Bp1 + (size_t)ko * Nw + p * bRow8);
            }
        }

        const u32* sA = smg + (ch & 1) * G_STAGE;
        const u32* sB = sA + G_STAGE_A;
        const u32* sAw = sA + (warpM * 64) * G_SA_LD;

        #pragma unroll
        for (int ks = 0; ks < 2; ks++) {
            const int kw = ks * 8;
            u32 af[4][4], bf[4][2];
            #pragma unroll
            for (int i = 0; i < 4; i++) {
                const u32* base = sAw + (i * 16 + g) * G_SA_LD + kw + tg;
                af[i][0] = base[0];
                af[i][1] = base[8 * G_SA_LD];
                af[i][2] = base[4];
                af[i][3] = base[8 * G_SA_LD + 4];
            }
            #pragma unroll
            for (int j = 0; j < 4; j++) {
                const u32* base = sB + (kw + tg) * G_SB_LD + bcolw + j * 8 + g;
                bf[j][0] = base[0];
                bf[j][1] = base[4 * G_SB_LD];
            }
            #pragma unroll
            for (int i = 0; i < 4; i++)
                #pragma unroll
                for (int j = 0; j < 4; j++)
                    mma_f16(c[i][j], af[i], bf[j]);
        }
    }

    #pragma unroll
    for (int i = 0; i < 4; i++) {
        const int r0e = row0 + warpM * 64 + i * 16 + g;
        #pragma unroll
        for (int j = 0; j < 4; j++) {
            const int col = col0 + warpN * 32 + j * 8 + 2 * tg;
            float bb0 = 0.f, bb1 = 0.f;
            if (bias) { bb0 = bias[col]; bb1 = bias[col + 1]; }
            *(float2*)(C + (size_t)r0e * Nw + col) =
                make_float2(c[i][j][0] + bb0, c[i][j][1] + bb1);
            *(float2*)(C + (size_t)(r0e + 8) * Nw + col) =
                make_float2(c[i][j][2] + bb0, c[i][j][3] + bb1);
        }
    }
}

// ---------------------------------------------------------------------------
// RoPE: fused Q+K, float4-vectorized (identical per-element math to R4 rope)
// ---------------------------------------------------------------------------
#define ROPE_QN (SEQ*NH*16)
#define ROPE_KN (SEQ*NKV*16)

__global__ void rope_kernel(const float* __restrict__ cosT,
                            const float* __restrict__ sinT)
{
    const int idx = blockIdx.x * blockDim.x + threadIdx.x;
    float* X; int nheads; int li;
    if (idx < ROPE_QN)                { X = g_Q; nheads = NH;  li = idx; }
    else if (idx < ROPE_QN + ROPE_KN) { X = g_K; nheads = NKV; li = idx - ROPE_QN; }
    else return;

    const int d4 = (li & 15) * 4;
    const int h = (li >> 4) % nheads;
    const int s = li / (16 * nheads);

    const float4 c1 = *(const float4*)&cosT[s * HD + d4];
    const float4 s1 = *(const float4*)&sinT[s * HD + d4];
    const float4 c2 = *(const float4*)&cosT[s * HD + d4 + 64];
    const float4 s2 = *(const float4*)&sinT[s * HD + d4 + 64];

    float4* p = (float4*)(X + (size_t)s * (nheads * HD) + h * HD + d4);
    const float4 x1 = p[0];
    const float4 x2 = p[16];   // +64 floats

    float4 y1, y2;
    y1.x = x1.x * c1.x - x2.x * s1.x;
    y1.y = x1.y * c1.y - x2.y * s1.y;
    y1.z = x1.z * c1.z - x2.z * s1.z;
    y1.w = x1.w * c1.w - x2.w * s1.w;
    y2.x = x2.x * c2.x + x1.x * s2.x;
    y2.y = x2.y * c2.y + x1.y * s2.y;
    y2.z = x2.z * c2.z + x1.z * s2.z;
    y2.w = x2.w * c2.w + x1.w * s2.w;
    p[0]  = y1;
    p[16] = y2;
}

// ---------------------------------------------------------------------------
// Full-fp16 flash attention with double-buffered single-barrier staging
// (round-14 verbatim, proven at 117us / 335.9us total).
// ---------------------------------------------------------------------------
#define KLD16 68
#define VLD16 136
#define SK16_WORDS (64*KLD16)                // 4352
#define SVT_WORDS  (32*VLD16)                // 4352
#define A_STG (SK16_WORDS + SVT_WORDS)       // 8704 words per stage
#define ATTN_SMEM (2*A_STG*4)                // 69632 B

__device__ __forceinline__ void attn_stage(
    u32* buf, int kt, int ntiles, int kvh, int t)
{
    u32* bK = buf;
    u32* bV = buf + SK16_WORDS;
    #pragma unroll
    for (int p = 0; p < 16; p++) {
        const int idx = p * 128 + t;
        const int key = idx >> 5;
        const int d4 = (idx & 31) * 4;
        const float4 kk =
            *(const float4*)&g_K[(size_t)(kt * 64 + key) * KVW + kvh * HD + d4];
        *(uint2*)(bK + key * KLD16 + (d4 >> 1)) =
            make_uint2(pack_h2(kk.x, kk.y), pack_h2(kk.z, kk.w));
    }
    #pragma unroll
    for (int p = 0; p < 8; p++) {
        const int idx = p * 128 + t;
        const int kp = idx >> 5;
        const int d4 = (idx & 31) * 4;
        const size_t base = (size_t)(kt * 64 + 2 * kp) * KVW + kvh * HD + d4;
        const float4 v0 = *(const float4*)&g_V[base];
        const float4 v1 = *(const float4*)&g_V[base + KVW];
        *(uint4*)(bV + kp * VLD16 + d4) = make_uint4(
            pack_h2(v0.x, v1.x), pack_h2(v0.y, v1.y),
            pack_h2(v0.z, v1.z), pack_h2(v0.w, v1.w));
    }
    if (kt + 1 < ntiles) {
        #pragma unroll
        for (int q2 = 0; q2 < 2; q2++) {
            const int li = t * 2 + q2;
            const int row = li >> 2, seg = li & 3;
            const char* ka = (const char*)
                &g_K[(size_t)((kt + 1) * 64 + row) * KVW + kvh * HD] + seg * 128;
            const char* va = (const char*)
                &g_V[(size_t)((kt + 1) * 64 + row) * KVW + kvh * HD] + seg * 128;
            prefetch_l1(ka);
            prefetch_l1(va);
        }
    }
}

__global__ void __launch_bounds__(128) attn_mma_kernel()
{
    extern __shared__ u32 smem[];

    const int t = threadIdx.x;
    const int lane = t & 31, wid = t >> 5;
    const int g = lane >> 2, tg = lane & 3;
    const int qt = 31 - blockIdx.x;          // heavy tiles first
    const int h  = blockIdx.y;
    const int kvh = h >> 3;
    const int qbase = qt * 64 + wid * 16;
    const int r0 = qbase + g, r1 = qbase + g + 8;

    u32 qf[8][4];
    const float* Qp = g_Q + (size_t)qbase * HIDDEN + h * HD;
    #pragma unroll
    for (int ks = 0; ks < 8; ks++) {
        const float2 a0 = *(const float2*)(Qp + (size_t)g * HIDDEN + ks * 16 + 2 * tg);
        const float2 a1 = *(const float2*)(Qp + (size_t)(g + 8) * HIDDEN + ks * 16 + 2 * tg);
        const float2 a2 = *(const float2*)(Qp + (size_t)g * HIDDEN + ks * 16 + 8 + 2 * tg);
        const float2 a3 = *(const float2*)(Qp + (size_t)(g + 8) * HIDDEN + ks * 16 + 8 + 2 * tg);
        qf[ks][0] = pack_h2(a0.x, a0.y);
        qf[ks][1] = pack_h2(a1.x, a1.y);
        qf[ks][2] = pack_h2(a2.x, a2.y);
        qf[ks][3] = pack_h2(a3.x, a3.y);
    }

    float o[16][4];
    #pragma unroll
    for (int n = 0; n < 16; n++)
        #pragma unroll
        for (int r = 0; r < 4; r++) o[n][r] = 0.f;
    float m0 = -1e30f, m1 = -1e30f, l0 = 0.f, l1 = 0.f;

    const int ntiles = qt + 1;

    attn_stage(smem, 0, ntiles, kvh, t);
    __syncthreads();

    for (int kt = 0; kt < ntiles; kt++) {
        const u32* sK16 = smem + (kt & 1) * A_STG;
        const u32* sVT  = sK16 + SK16_WORDS;

        if (kt * 64 <= qbase + 15) {
            float c[8][4];
            #pragma unroll
            for (int j = 0; j < 8; j++)
                #pragma unroll
                for (int r = 0; r < 4; r++) c[j][r] = 0.f;

            #pragma unroll
            for (int ks = 0; ks < 8; ks++) {
                #pragma unroll
                for (int j = 0; j < 8; j++) {
                    u32 bf[2];
                    const u32* bb = sK16 + (j * 8 + g) * KLD16 + ks * 8 + tg;
                    bf[0] = bb[0];
                    bf[1] = bb[4];
                    mma_f16(c[j], qf[ks], bf);
                }
            }

            const bool diag = (kt * 64 + 63 > qbase);
            #pragma unroll
            for (int j = 0; j < 8; j++) {
                const int key = kt * 64 + j * 8 + 2 * tg;
                c[j][0] *= ATT_SCALE; c[j][1] *= ATT_SCALE;
                c[j][2] *= ATT_SCALE; c[j][3] *= ATT_SCALE;
                if (diag) {
                    if (key     > r0) c[j][0] = -1e30f;
                    if (key + 1 > r0) c[j][1] = -1e30f;
                    if (key     > r1) c[j][2] = -1e30f;
                    if (key + 1 > r1) c[j][3] = -1e30f;
                }
            }

            float mx0 = m0, mx1 = m1;
            #pragma unroll
            for (int j = 0; j < 8; j++) {
                mx0 = fmaxf(mx0, fmaxf(c[j][0], c[j][1]));
                mx1 = fmaxf(mx1, fmaxf(c[j][2], c[j][3]));
            }
            mx0 = fmaxf(mx0, __shfl_xor_sync(0xffffffffu, mx0, 1));
            mx0 = fmaxf(mx0, __shfl_xor_sync(0xffffffffu, mx0, 2));
            mx1 = fmaxf(mx1, __shfl_xor_sync(0xffffffffu, mx1, 1));
            mx1 = fmaxf(mx1, __shfl_xor_sync(0xffffffffu, mx1, 2));
            const float corr0 = __expf(m0 - mx0);
            const float corr1 = __expf(m1 - mx1);
            m0 = mx0; m1 = mx1;
            l0 *= corr0; l1 *= corr1;
            #pragma unroll
            for (int n = 0; n < 16; n++) {
                o[n][0] *= corr0; o[n][1] *= corr0;
                o[n][2] *= corr1; o[n][3] *= corr1;
            }

            float s0 = 0.f, s1 = 0.f;
            #pragma unroll
            for (int kg = 0; kg < 4; kg++) {
                const int j0 = kg * 2, j1 = kg * 2 + 1;
                const float e00a = __expf(c[j0][0] - m0);
                const float e01a = __expf(c[j0][1] - m0);
                const float e10a = __expf(c[j0][2] - m1);
                const float e11a = __expf(c[j0][3] - m1);
                const float e00b = __expf(c[j1][0] - m0);
                const float e01b = __expf(c[j1][1] - m0);
                const float e10b = __expf(c[j1][2] - m1);
                const float e11b = __expf(c[j1][3] - m1);
                s0 += e00a + e01a + e00b + e01b;
                s1 += e10a + e11a + e10b + e11b;

                u32 af[4];
                af[0] = pack_h2(e00a, e01a);
                af[1] = pack_h2(e10a, e11a);
                af[2] = pack_h2(e00b, e01b);
                af[3] = pack_h2(e10b, e11b);

                #pragma unroll
                for (int n = 0; n < 16; n++) {
                    u32 bf[2];
                    const u32* bb = sVT + (kg * 8 + tg) * VLD16 + n * 8 + g;
                    bf[0] = bb[0];
                    bf[1] = bb[4 * VLD16];
                    mma_f16(o[n], af, bf);
                }
            }
            s0 += __shfl_xor_sync(0xffffffffu, s0, 1);
            s0 += __shfl_xor_sync(0xffffffffu, s0, 2);
            s1 += __shfl_xor_sync(0xffffffffu, s1, 1);
            s1 += __shfl_xor_sync(0xffffffffu, s1, 2);
            l0 += s0; l1 += s1;
        }

        if (kt + 1 < ntiles)
            attn_stage(smem + ((kt + 1) & 1) * A_STG, kt + 1, ntiles, kvh, t);

        __syncthreads();
    }

    const float inv0 = 1.f / l0;
    const float inv1 = 1.f / l1;
    float* cp0 = g_C + (size_t)r0 * HIDDEN + h * HD;
    float* cp1 = g_C + (size_t)r1 * HIDDEN + h * HD;
    #pragma unroll
    for (int n = 0; n < 16; n++) {
        const int col = n * 8 + 2 * tg;
        *(float2*)(cp0 + col) = make_float2(o[n][0] * inv0, o[n][1] * inv0);
        *(float2*)(cp1 + col) = make_float2(o[n][2] * inv1, o[n][3] * inv1);
    }
}

// ---------------------------------------------------------------------------
extern "C" void kernel_launch(void* const* d_in, const int* in_sizes, int n_in,
                              void* d_out, int out_size)
{
    const float* hs   = (const float*)d_in[0];
    const float* cosT = (const float*)d_in[1];
    const float* sinT = (const float*)d_in[2];
    // d_in[3] = attention_mask (pure causal; applied analytically)
    const float* Wq = (const float*)d_in[4];
    const float* bq = (const float*)d_in[5];
    const float* Wk = (const float*)d_in[6];
    const float* bk = (const float*)d_in[7];
    const float* Wv = (const float*)d_in[8];
    const float* bv = (const float*)d_in[9];
    const float* Wo = (const float*)d_in[10];
    float* out = (float*)d_out;

    cudaFuncSetAttribute(mma_gemm_kernel,
                         cudaFuncAttributeMaxDynamicSharedMemorySize, G_SMEM);
    cudaFuncSetAttribute(attn_mma_kernel,
                         cudaFuncAttributeMaxDynamicSharedMemorySize, ATTN_SMEM);

    // fused QKV projection: blocks 0-15 -> Q, 16-17 -> K, 18-19 -> V
    mma_gemm_kernel<<<dim3(20, 16), 256, G_SMEM>>>(
        hs, Wq, Wk, Wv, bq, bk, bv, nullptr, 1);

    // fused vectorized RoPE (Q + K)
    rope_kernel<<<(ROPE_QN + ROPE_KN + 255) / 256, 256>>>(cosT, sinT);

    attn_mma_kernel<<<dim3(32, 16), 128, ATTN_SMEM>>>();

    // O projection
    mma_gemm_kernel<<<dim3(16, 16), 256, G_SMEM>>>(
        g_C, Wo, nullptr, nullptr, nullptr, nullptr, nullptr, out, 0);
}